// round 14
// baseline (speedup 1.0000x reference)
#include <cuda_runtime.h>
#include <cuda_fp16.h>
#include <cstdint>

#define CIN  256
#define COUT 256
#define HDIM 64
#define WDIM 64
#define HW   4096
#define BATCH 8

// Scratch — static device globals (alloc-free rule). q,k,v all fp16.
__device__ __align__(128) __half g_qh[(size_t)BATCH * COUT * HW];
__device__ __align__(128) __half g_kh[(size_t)BATCH * COUT * HW];
__device__ __align__(128) __half g_vh[(size_t)BATCH * COUT * HW];

// ---------------------------------------------------------------------------
// helpers
// ---------------------------------------------------------------------------
// fp32 pair -> packed f16x2 (low 16 bits = a, high = b)
__device__ __forceinline__ uint32_t f2h2(float a, float b) {
    uint32_t r;
    asm("cvt.rn.f16x2.f32 %0, %1, %2;" : "=r"(r) : "f"(b), "f"(a));
    return r;
}
__device__ __forceinline__ void h8_to_f8(uint4 u, float* f) {
    float2 p;
    p = __half22float2(*(__half2*)&u.x); f[0] = p.x; f[1] = p.y;
    p = __half22float2(*(__half2*)&u.y); f[2] = p.x; f[3] = p.y;
    p = __half22float2(*(__half2*)&u.z); f[4] = p.x; f[5] = p.y;
    p = __half22float2(*(__half2*)&u.w); f[6] = p.x; f[7] = p.y;
}

#define LDSM_X4(r0, r1, r2, r3, addr)                                           \
    asm volatile("ldmatrix.sync.aligned.m8n8.x4.shared.b16 {%0,%1,%2,%3}, [%4];"\
                 : "=r"(r0), "=r"(r1), "=r"(r2), "=r"(r3) : "r"(addr))

#define LDSM_X4_T(r0, r1, r2, r3, addr)                                         \
    asm volatile("ldmatrix.sync.aligned.m8n8.x4.trans.shared.b16 {%0,%1,%2,%3}, [%4];"\
                 : "=r"(r0), "=r"(r1), "=r"(r2), "=r"(r3) : "r"(addr))

#define MMAF16(d, a, b0, b1)                                                    \
    asm volatile("mma.sync.aligned.m16n8k16.row.col.f32.f16.f16.f32 "           \
        "{%0,%1,%2,%3}, {%4,%5,%6,%7}, {%8,%9}, {%0,%1,%2,%3};"                 \
        : "+f"((d)[0]), "+f"((d)[1]), "+f"((d)[2]), "+f"((d)[3])                \
        : "r"((a)[0]), "r"((a)[1]), "r"((a)[2]), "r"((a)[3]),                   \
          "r"(b0), "r"(b1))

#define A_STRIDE 40     // f16 elems per row of 128x32 A tile (80B, padded)
#define B_STRIDE 136    // f16 elems per row of 32x128 B tile (272B, padded)

// ---------------------------------------------------------------------------
// GEMM: C[o,p] = sum_i W[o,i] * X[i,p] per batch image, single-term fp16 MMA.
// 128x128 tile, K-blocks of 32, double-buffered SMEM, 8 warps, 2 CTAs/SM.
// Grid: (6, 256) with bx = z*2 + m-tile (FASTEST) so the 6 CTAs sharing one
// n0 B-slab are co-resident -> x/y pulled through L2 once instead of 4x/2x.
// All outputs stored fp16.
// ---------------------------------------------------------------------------
__global__ __launch_bounds__(256, 2)
void qkv_gemm_fp16(const float* __restrict__ wq, const float* __restrict__ wk,
                   const float* __restrict__ wv, const float* __restrict__ x,
                   const float* __restrict__ y)
{
    __shared__ __align__(16) __half As[2][128 * A_STRIDE];   // 2 x 10240 B
    __shared__ __align__(16) __half Bs[2][32 * B_STRIDE];    // 2 x  8704 B

    const int z  = blockIdx.x >> 1;              // 0=q, 1=k, 2=v
    const int m0 = (blockIdx.x & 1) * 128;
    const int n0 = blockIdx.y * 128;

    const float* Wm = (z == 0) ? wq : (z == 1 ? wk : wv);
    const float* X  = (z == 0) ? y : x;

    const int b   = n0 >> 12;
    const int hw0 = n0 & 4095;
    const float* Xb = X + (size_t)b * CIN * HW + hw0;

    const int tid  = threadIdx.x;
    const int lane = tid & 31;
    const int wid  = tid >> 5;
    const int wm   = (wid >> 1) * 32;   // warp m offset (0,32,64,96)
    const int wn   = (wid & 1) * 64;    // warp n offset (0,64)

    const int acol = (tid & 7) * 4;     // A: 4 float4/thread
    const int arow = tid >> 3;
    const int bcol = (tid & 31) * 4;    // B: 4 float4/thread
    const int brow = tid >> 5;

    float acc[2][8][4];
    #pragma unroll
    for (int i = 0; i < 2; i++)
        #pragma unroll
        for (int j = 0; j < 8; j++)
            #pragma unroll
            for (int q = 0; q < 4; q++)
                acc[i][j][q] = 0.0f;

    float4 ra[4], rb[4];

    // ---- prologue: k-block 0 -> buf0; k-block 1 -> registers ----
    #pragma unroll
    for (int i = 0; i < 4; i++)
        ra[i] = *(const float4*)(Wm + (size_t)(m0 + arow + i * 32) * CIN + acol);
    #pragma unroll
    for (int i = 0; i < 4; i++)
        rb[i] = *(const float4*)(Xb + (size_t)(brow + i * 8) * HW + bcol);
    #pragma unroll
    for (int i = 0; i < 4; i++) {
        *(uint2*)((char*)As[0] + (arow + i * 32) * 80 + acol * 2) =
            make_uint2(f2h2(ra[i].x, ra[i].y), f2h2(ra[i].z, ra[i].w));
        *(uint2*)((char*)Bs[0] + (brow + i * 8) * 272 + bcol * 2) =
            make_uint2(f2h2(rb[i].x, rb[i].y), f2h2(rb[i].z, rb[i].w));
    }
    #pragma unroll
    for (int i = 0; i < 4; i++)
        ra[i] = *(const float4*)(Wm + (size_t)(m0 + arow + i * 32) * CIN + 32 + acol);
    #pragma unroll
    for (int i = 0; i < 4; i++)
        rb[i] = *(const float4*)(Xb + (size_t)(32 + brow + i * 8) * HW + bcol);
    __syncthreads();

    for (int it = 0; it < 8; it++) {
        // STS: k-block it+1 (in regs) -> buffer (it+1)&1.
        if (it < 7) {
            __half* dA = As[(it + 1) & 1];
            __half* dB = Bs[(it + 1) & 1];
            #pragma unroll
            for (int i = 0; i < 4; i++) {
                *(uint2*)((char*)dA + (arow + i * 32) * 80 + acol * 2) =
                    make_uint2(f2h2(ra[i].x, ra[i].y), f2h2(ra[i].z, ra[i].w));
                *(uint2*)((char*)dB + (brow + i * 8) * 272 + bcol * 2) =
                    make_uint2(f2h2(rb[i].x, rb[i].y), f2h2(rb[i].z, rb[i].w));
            }
        }
        // LDG: k-block it+2 -> registers
        if (it < 6) {
            const int k0 = (it + 2) * 32;
            #pragma unroll
            for (int i = 0; i < 4; i++)
                ra[i] = *(const float4*)(Wm + (size_t)(m0 + arow + i * 32) * CIN + k0 + acol);
            #pragma unroll
            for (int i = 0; i < 4; i++)
                rb[i] = *(const float4*)(Xb + (size_t)(k0 + brow + i * 8) * HW + bcol);
        }

        // ---- Compute: 2 ksteps of 16 from buffer it&1 ----
        const uint32_t sA = (uint32_t)__cvta_generic_to_shared(As[it & 1]);
        const uint32_t sB = (uint32_t)__cvta_generic_to_shared(Bs[it & 1]);
        #pragma unroll
        for (int ks = 0; ks < 2; ks++) {
            const int kb = ks * 16;
            uint32_t af[2][4];
            #pragma unroll
            for (int mt = 0; mt < 2; mt++) {
                const uint32_t off =
                    (uint32_t)((wm + mt * 16 + (lane & 15)) * A_STRIDE + kb + (lane >> 4) * 8) * 2;
                LDSM_X4(af[mt][0], af[mt][1], af[mt][2], af[mt][3], sA + off);
            }
            #pragma unroll
            for (int ntp = 0; ntp < 4; ntp++) {
                const int nb = wn + ntp * 16;
                const uint32_t off =
                    (uint32_t)((kb + (lane & 15)) * B_STRIDE + nb + (lane >> 4) * 8) * 2;
                uint32_t bf[4];
                LDSM_X4_T(bf[0], bf[1], bf[2], bf[3], sB + off);
                #pragma unroll
                for (int mt = 0; mt < 2; mt++) {
                    #pragma unroll
                    for (int h2 = 0; h2 < 2; h2++)
                        MMAF16(acc[mt][ntp * 2 + h2], af[mt], bf[h2 * 2], bf[h2 * 2 + 1]);
                }
            }
        }
        __syncthreads();
    }

    // ---- Epilogue: all outputs fp16 ----
    __half* Hb = ((z == 0) ? g_qh : (z == 1 ? g_kh : g_vh)) + (size_t)b * COUT * HW + hw0;
    #pragma unroll
    for (int mt = 0; mt < 2; mt++) {
        const int m = wm + mt * 16 + (lane >> 2);
        #pragma unroll
        for (int nt = 0; nt < 8; nt++) {
            const int n = wn + nt * 8 + (lane & 3) * 2;
            const float* d = acc[mt][nt];
            *(uint32_t*)(Hb + (size_t)(m0 + m) * HW + n)     = f2h2(d[0], d[1]);
            *(uint32_t*)(Hb + (size_t)(m0 + m + 8) * HW + n) = f2h2(d[2], d[3]);
        }
    }
}

// ---------------------------------------------------------------------------
// Window attention: SMEM-tiled, 4 px/thread, zero halo, no max-subtraction.
// q,k,v all read as fp16 (k,v converted to fp32 during the SMEM fill).
// ---------------------------------------------------------------------------
__global__ __launch_bounds__(256)
void attn_kernel2(const float* __restrict__ rel_h, const float* __restrict__ rel_w,
                  float* __restrict__ out)
{
    __shared__ float Ks[18][68];
    __shared__ float Vs[18][68];

    const int tid = threadIdx.x;
    const int h0  = blockIdx.x * 16;
    const int c   = blockIdx.y;
    const int b   = blockIdx.z;
    const size_t plane = ((size_t)b * COUT + c) * HW;
    const __half* kp = g_kh + plane;
    const __half* vp = g_vh + plane;

    // Single-pass fill: 18 rows x 8 segments of 8 halves. OOB -> 0.
    if (tid < 144) {
        const int r   = tid >> 3;
        const int seg = (tid & 7) * 8;
        const int gh  = h0 - 1 + r;
        float kf[8] = {0, 0, 0, 0, 0, 0, 0, 0};
        float vf[8] = {0, 0, 0, 0, 0, 0, 0, 0};
        if ((unsigned)gh < (unsigned)HDIM) {
            h8_to_f8(*(const uint4*)(kp + gh * WDIM + seg), kf);
            h8_to_f8(*(const uint4*)(vp + gh * WDIM + seg), vf);
        }
        #pragma unroll
        for (int j = 0; j < 8; j++) {
            Ks[r][seg + 1 + j] = kf[j];
            Vs[r][seg + 1 + j] = vf[j];
        }
    }
    if (tid < 18) {
        Ks[tid][0] = 0.f; Ks[tid][65] = 0.f;
        Vs[tid][0] = 0.f; Vs[tid][65] = 0.f;
    }

    float b9[9];
    {
        const bool use_h = (c < 128);
        float bias[3];
        if (use_h) {
            bias[0] = rel_h[c * 3 + 0]; bias[1] = rel_h[c * 3 + 1]; bias[2] = rel_h[c * 3 + 2];
        } else {
            bias[0] = rel_w[(c - 128) * 3 + 0]; bias[1] = rel_w[(c - 128) * 3 + 1];
            bias[2] = rel_w[(c - 128) * 3 + 2];
        }
        #pragma unroll
        for (int dr = 0; dr < 3; dr++)
            #pragma unroll
            for (int dj = 0; dj < 3; dj++)
                b9[dr * 3 + dj] = use_h ? bias[dr] : bias[dj];
    }
    __syncthreads();

    const int lr = tid >> 4;
    const int w0 = (tid & 15) * 4;
    const int h  = h0 + lr;

    float q[4];
    {
        const uint2 qu = *(const uint2*)(g_qh + plane + h * WDIM + w0);
        float2 p = __half22float2(*(__half2*)&qu.x); q[0] = p.x; q[1] = p.y;
        p = __half22float2(*(__half2*)&qu.y);        q[2] = p.x; q[3] = p.y;
    }

    float kk[3][6], vv[3][6];
    #pragma unroll
    for (int dr = 0; dr < 3; dr++) {
        const float* krow = &Ks[lr + dr][w0];
        const float* vrow = &Vs[lr + dr][w0];
        const float4 ka = *(const float4*)krow;
        const float2 kb = *(const float2*)(krow + 4);
        const float4 va = *(const float4*)vrow;
        const float2 vb = *(const float2*)(vrow + 4);
        kk[dr][0] = ka.x; kk[dr][1] = ka.y; kk[dr][2] = ka.z;
        kk[dr][3] = ka.w; kk[dr][4] = kb.x; kk[dr][5] = kb.y;
        vv[dr][0] = va.x; vv[dr][1] = va.y; vv[dr][2] = va.z;
        vv[dr][3] = va.w; vv[dr][4] = vb.x; vv[dr][5] = vb.y;
    }

    float res[4];
    #pragma unroll
    for (int p = 0; p < 4; p++) {
        float den = 0.f, num = 0.f;
        #pragma unroll
        for (int dr = 0; dr < 3; dr++)
            #pragma unroll
            for (int dj = 0; dj < 3; dj++) {
                const float e = __expf(q[p] * (kk[dr][p + dj] + b9[dr * 3 + dj]));
                den += e;
                num = fmaf(e, vv[dr][p + dj], num);
            }
        res[p] = __fdividef(num, den);
    }

    *(float4*)(out + plane + h * WDIM + w0) = make_float4(res[0], res[1], res[2], res[3]);
}

// ---------------------------------------------------------------------------
extern "C" void kernel_launch(void* const* d_in, const int* in_sizes, int n_in,
                              void* d_out, int out_size)
{
    const float* x     = (const float*)d_in[0];
    const float* y     = (const float*)d_in[1];
    const float* wq    = (const float*)d_in[2];
    const float* wk    = (const float*)d_in[3];
    const float* wv    = (const float*)d_in[4];
    const float* rel_h = (const float*)d_in[5];
    const float* rel_w = (const float*)d_in[6];
    float* out = (float*)d_out;

    dim3 ggrid(6, BATCH * HW / 128, 1);            // bx = z*2+m0 (fastest), by = n0
    qkv_gemm_fp16<<<ggrid, 256>>>(wq, wk, wv, x, y);

    dim3 agrid(HDIM / 16, COUT, BATCH);            // (4, 256, 8)
    attn_kernel2<<<agrid, 256>>>(rel_h, rel_w, out);
}

// round 15
// speedup vs baseline: 1.0409x; 1.0409x over previous
#include <cuda_runtime.h>
#include <cuda_fp16.h>
#include <cstdint>

#define CIN  256
#define COUT 256
#define HDIM 64
#define WDIM 64
#define HW   4096
#define BATCH 8

// Scratch — static device globals (alloc-free rule). q fp32; k,v fp16; W fp16.
__device__ __align__(128) float  g_q[(size_t)BATCH * COUT * HW];
__device__ __align__(128) __half g_kh[(size_t)BATCH * COUT * HW];
__device__ __align__(128) __half g_vh[(size_t)BATCH * COUT * HW];
__device__ __align__(128) __half g_wh[3 * 65536];

// ---------------------------------------------------------------------------
// helpers
// ---------------------------------------------------------------------------
// fp32 pair -> packed f16x2 (low 16 bits = a, high = b)
__device__ __forceinline__ uint32_t f2h2(float a, float b) {
    uint32_t r;
    asm("cvt.rn.f16x2.f32 %0, %1, %2;" : "=r"(r) : "f"(b), "f"(a));
    return r;
}
__device__ __forceinline__ void h8_to_f8(uint4 u, float* f) {
    float2 p;
    p = __half22float2(*(__half2*)&u.x); f[0] = p.x; f[1] = p.y;
    p = __half22float2(*(__half2*)&u.y); f[2] = p.x; f[3] = p.y;
    p = __half22float2(*(__half2*)&u.z); f[4] = p.x; f[5] = p.y;
    p = __half22float2(*(__half2*)&u.w); f[6] = p.x; f[7] = p.y;
}

#define LDSM_X4(r0, r1, r2, r3, addr)                                           \
    asm volatile("ldmatrix.sync.aligned.m8n8.x4.shared.b16 {%0,%1,%2,%3}, [%4];"\
                 : "=r"(r0), "=r"(r1), "=r"(r2), "=r"(r3) : "r"(addr))

#define LDSM_X4_T(r0, r1, r2, r3, addr)                                         \
    asm volatile("ldmatrix.sync.aligned.m8n8.x4.trans.shared.b16 {%0,%1,%2,%3}, [%4];"\
                 : "=r"(r0), "=r"(r1), "=r"(r2), "=r"(r3) : "r"(addr))

#define MMAF16(d, a, b0, b1)                                                    \
    asm volatile("mma.sync.aligned.m16n8k16.row.col.f32.f16.f16.f32 "           \
        "{%0,%1,%2,%3}, {%4,%5,%6,%7}, {%8,%9}, {%0,%1,%2,%3};"                 \
        : "+f"((d)[0]), "+f"((d)[1]), "+f"((d)[2]), "+f"((d)[3])                \
        : "r"((a)[0]), "r"((a)[1]), "r"((a)[2]), "r"((a)[3]),                   \
          "r"(b0), "r"(b1))

#define CP16(dst, src)                                                          \
    asm volatile("cp.async.cg.shared.global [%0], [%1], 16;"                    \
                 :: "r"(dst), "l"(src) : "memory")
#define CP_COMMIT asm volatile("cp.async.commit_group;" ::: "memory")
#define CP_WAIT0  asm volatile("cp.async.wait_group 0;" ::: "memory")

#define A_STRIDE 40     // f16 elems per row of 128x32 A tile (80B, padded)
#define B_STRIDE 136    // f16 elems per row of 32x128 B tile (272B, padded)

// ---------------------------------------------------------------------------
// Prep: convert W matrices to fp16 (once; removes A conversion from GEMM loop).
// grid (64, 3), 256 threads; each thread one float4 -> 4 halves.
// ---------------------------------------------------------------------------
__global__ __launch_bounds__(256)
void prep_w(const float* __restrict__ wq, const float* __restrict__ wk,
            const float* __restrict__ wv)
{
    const int z = blockIdx.y;
    const float* src = (z == 0) ? wq : (z == 1 ? wk : wv);
    const int i4 = blockIdx.x * 256 + threadIdx.x;
    const float4 a = *(const float4*)(src + i4 * 4);
    *(uint2*)(g_wh + z * 65536 + i4 * 4) =
        make_uint2(f2h2(a.x, a.y), f2h2(a.z, a.w));
}

// ---------------------------------------------------------------------------
// GEMM: C[o,p] = sum_i W[o,i] * X[i,p] per batch image, single-term fp16 MMA.
// 128x128 tile, K-blocks of 32, 8 warps, 2 CTAs/SM.
// A: cp.async double-buffered from pre-converted fp16 W (no regs/cvt/STS).
// B: register-staged fp32->fp16 (R11 pattern: STS prev -> LDG next+1 -> MMA).
// Grid (6, 256): bx = z*2 + m-tile, by = n0-tile.
// z=0 writes q fp32; z=1/2 write k/v fp16.
// ---------------------------------------------------------------------------
__global__ __launch_bounds__(256, 2)
void qkv_gemm_fp16(const float* __restrict__ x, const float* __restrict__ y)
{
    __shared__ __align__(16) __half As[2][128 * A_STRIDE];   // 2 x 10240 B
    __shared__ __align__(16) __half Bs[2][32 * B_STRIDE];    // 2 x  8704 B

    const int z  = blockIdx.x >> 1;              // 0=q, 1=k, 2=v
    const int m0 = (blockIdx.x & 1) * 128;
    const int n0 = blockIdx.y * 128;

    const __half* Wh = g_wh + z * 65536;
    const float*  X  = (z == 0) ? y : x;

    const int b   = n0 >> 12;
    const int hw0 = n0 & 4095;
    const float* Xb = X + (size_t)b * CIN * HW + hw0;

    const int tid  = threadIdx.x;
    const int lane = tid & 31;
    const int wid  = tid >> 5;
    const int wm   = (wid >> 1) * 32;   // warp m offset (0,32,64,96)
    const int wn   = (wid & 1) * 64;    // warp n offset (0,64)

    // A cp.async mapping: 2 chunks of 16B per thread. chunk c: row = c>>2,
    // sub = c&3 (16B = 8 halves within the 64B source row).
    const int ac0 = tid * 2;
    const int ar0 = ac0 >> 2, as0 = (ac0 & 3) * 8;
    const int ar1 = (ac0 + 1) >> 2, as1 = ((ac0 + 1) & 3) * 8;

    // B-load mapping: 4 float4/thread
    const int bcol = (tid & 31) * 4;    // 0..124
    const int brow = tid >> 5;          // 0..7 (+8*i)

    float acc[2][8][4];
    #pragma unroll
    for (int i = 0; i < 2; i++)
        #pragma unroll
        for (int j = 0; j < 8; j++)
            #pragma unroll
            for (int q = 0; q < 4; q++)
                acc[i][j][q] = 0.0f;

    float4 rb[4];

    // ---- prologue ----
    // A k-block 0 -> buf0 via cp.async
    {
        const uint32_t d0 = (uint32_t)__cvta_generic_to_shared(As[0]);
        CP16(d0 + ar0 * 80 + as0 * 2, Wh + (m0 + ar0) * 256 + as0);
        CP16(d0 + ar1 * 80 + as1 * 2, Wh + (m0 + ar1) * 256 + as1);
        CP_COMMIT;
    }
    // B k-block 0 -> buf0 (regs, cvt, STS)
    #pragma unroll
    for (int i = 0; i < 4; i++)
        rb[i] = *(const float4*)(Xb + (size_t)(brow + i * 8) * HW + bcol);
    #pragma unroll
    for (int i = 0; i < 4; i++)
        *(uint2*)((char*)Bs[0] + (brow + i * 8) * 272 + bcol * 2) =
            make_uint2(f2h2(rb[i].x, rb[i].y), f2h2(rb[i].z, rb[i].w));
    // B k-block 1 -> regs
    #pragma unroll
    for (int i = 0; i < 4; i++)
        rb[i] = *(const float4*)(Xb + (size_t)(32 + brow + i * 8) * HW + bcol);
    CP_WAIT0;
    __syncthreads();

    for (int it = 0; it < 8; it++) {
        // cp.async A(it+1) into the other buffer (free since prev barrier).
        if (it < 7) {
            const int k0 = (it + 1) * 32;
            const uint32_t d = (uint32_t)__cvta_generic_to_shared(As[(it + 1) & 1]);
            CP16(d + ar0 * 80 + as0 * 2, Wh + (m0 + ar0) * 256 + k0 + as0);
            CP16(d + ar1 * 80 + as1 * 2, Wh + (m0 + ar1) * 256 + k0 + as1);
            CP_COMMIT;
        }
        // STS: B k-block it+1 (in regs) -> buffer (it+1)&1.
        if (it < 7) {
            __half* dB = Bs[(it + 1) & 1];
            #pragma unroll
            for (int i = 0; i < 4; i++)
                *(uint2*)((char*)dB + (brow + i * 8) * 272 + bcol * 2) =
                    make_uint2(f2h2(rb[i].x, rb[i].y), f2h2(rb[i].z, rb[i].w));
        }
        // LDG: B k-block it+2 -> registers
        if (it < 6) {
            const int k0 = (it + 2) * 32;
            #pragma unroll
            for (int i = 0; i < 4; i++)
                rb[i] = *(const float4*)(Xb + (size_t)(k0 + brow + i * 8) * HW + bcol);
        }

        // ---- Compute: 2 ksteps of 16 from buffer it&1 ----
        const uint32_t sA = (uint32_t)__cvta_generic_to_shared(As[it & 1]);
        const uint32_t sB = (uint32_t)__cvta_generic_to_shared(Bs[it & 1]);
        #pragma unroll
        for (int ks = 0; ks < 2; ks++) {
            const int kb = ks * 16;
            uint32_t af[2][4];
            #pragma unroll
            for (int mt = 0; mt < 2; mt++) {
                const uint32_t off =
                    (uint32_t)((wm + mt * 16 + (lane & 15)) * A_STRIDE + kb + (lane >> 4) * 8) * 2;
                LDSM_X4(af[mt][0], af[mt][1], af[mt][2], af[mt][3], sA + off);
            }
            #pragma unroll
            for (int ntp = 0; ntp < 4; ntp++) {
                const int nb = wn + ntp * 16;
                const uint32_t off =
                    (uint32_t)((kb + (lane & 15)) * B_STRIDE + nb + (lane >> 4) * 8) * 2;
                uint32_t bf[4];
                LDSM_X4_T(bf[0], bf[1], bf[2], bf[3], sB + off);
                #pragma unroll
                for (int mt = 0; mt < 2; mt++) {
                    #pragma unroll
                    for (int h2 = 0; h2 < 2; h2++)
                        MMAF16(acc[mt][ntp * 2 + h2], af[mt], bf[h2 * 2], bf[h2 * 2 + 1]);
                }
            }
        }
        CP_WAIT0;           // A(it+1) landed (covered by the MMA phase)
        __syncthreads();
    }

    // ---- Epilogue ----
    if (z == 0) {
        float* Cb = g_q + (size_t)b * COUT * HW + hw0;
        #pragma unroll
        for (int mt = 0; mt < 2; mt++) {
            const int m = wm + mt * 16 + (lane >> 2);
            #pragma unroll
            for (int nt = 0; nt < 8; nt++) {
                const int n = wn + nt * 8 + (lane & 3) * 2;
                const float* d = acc[mt][nt];
                *(float2*)(Cb + (size_t)(m0 + m) * HW + n)     = make_float2(d[0], d[1]);
                *(float2*)(Cb + (size_t)(m0 + m + 8) * HW + n) = make_float2(d[2], d[3]);
            }
        }
    } else {
        __half* Hb = ((z == 1) ? g_kh : g_vh) + (size_t)b * COUT * HW + hw0;
        #pragma unroll
        for (int mt = 0; mt < 2; mt++) {
            const int m = wm + mt * 16 + (lane >> 2);
            #pragma unroll
            for (int nt = 0; nt < 8; nt++) {
                const int n = wn + nt * 8 + (lane & 3) * 2;
                const float* d = acc[mt][nt];
                *(uint32_t*)(Hb + (size_t)(m0 + m) * HW + n)     = f2h2(d[0], d[1]);
                *(uint32_t*)(Hb + (size_t)(m0 + m + 8) * HW + n) = f2h2(d[2], d[3]);
            }
        }
    }
}

// ---------------------------------------------------------------------------
// Window attention: SMEM-tiled, 4 px/thread, zero halo, no max-subtraction.
// q fp32; k,v fp16 (converted to fp32 during the single-pass SMEM fill).
// ---------------------------------------------------------------------------
__global__ __launch_bounds__(256)
void attn_kernel2(const float* __restrict__ rel_h, const float* __restrict__ rel_w,
                  float* __restrict__ out)
{
    __shared__ float Ks[18][68];
    __shared__ float Vs[18][68];

    const int tid = threadIdx.x;
    const int h0  = blockIdx.x * 16;
    const int c   = blockIdx.y;
    const int b   = blockIdx.z;
    const size_t plane = ((size_t)b * COUT + c) * HW;
    const __half* kp = g_kh + plane;
    const __half* vp = g_vh + plane;

    // Single-pass fill: 18 rows x 8 segments of 8 halves. OOB -> 0.
    if (tid < 144) {
        const int r   = tid >> 3;
        const int seg = (tid & 7) * 8;
        const int gh  = h0 - 1 + r;
        float kf[8] = {0, 0, 0, 0, 0, 0, 0, 0};
        float vf[8] = {0, 0, 0, 0, 0, 0, 0, 0};
        if ((unsigned)gh < (unsigned)HDIM) {
            h8_to_f8(*(const uint4*)(kp + gh * WDIM + seg), kf);
            h8_to_f8(*(const uint4*)(vp + gh * WDIM + seg), vf);
        }
        #pragma unroll
        for (int j = 0; j < 8; j++) {
            Ks[r][seg + 1 + j] = kf[j];
            Vs[r][seg + 1 + j] = vf[j];
        }
    }
    if (tid < 18) {
        Ks[tid][0] = 0.f; Ks[tid][65] = 0.f;
        Vs[tid][0] = 0.f; Vs[tid][65] = 0.f;
    }

    float b9[9];
    {
        const bool use_h = (c < 128);
        float bias[3];
        if (use_h) {
            bias[0] = rel_h[c * 3 + 0]; bias[1] = rel_h[c * 3 + 1]; bias[2] = rel_h[c * 3 + 2];
        } else {
            bias[0] = rel_w[(c - 128) * 3 + 0]; bias[1] = rel_w[(c - 128) * 3 + 1];
            bias[2] = rel_w[(c - 128) * 3 + 2];
        }
        #pragma unroll
        for (int dr = 0; dr < 3; dr++)
            #pragma unroll
            for (int dj = 0; dj < 3; dj++)
                b9[dr * 3 + dj] = use_h ? bias[dr] : bias[dj];
    }
    __syncthreads();

    const int lr = tid >> 4;
    const int w0 = (tid & 15) * 4;
    const int h  = h0 + lr;

    const float4 q4 = *(const float4*)(g_q + plane + h * WDIM + w0);
    const float q[4] = {q4.x, q4.y, q4.z, q4.w};

    float kk[3][6], vv[3][6];
    #pragma unroll
    for (int dr = 0; dr < 3; dr++) {
        const float* krow = &Ks[lr + dr][w0];
        const float* vrow = &Vs[lr + dr][w0];
        const float4 ka = *(const float4*)krow;
        const float2 kb = *(const float2*)(krow + 4);
        const float4 va = *(const float4*)vrow;
        const float2 vb = *(const float2*)(vrow + 4);
        kk[dr][0] = ka.x; kk[dr][1] = ka.y; kk[dr][2] = ka.z;
        kk[dr][3] = ka.w; kk[dr][4] = kb.x; kk[dr][5] = kb.y;
        vv[dr][0] = va.x; vv[dr][1] = va.y; vv[dr][2] = va.z;
        vv[dr][3] = va.w; vv[dr][4] = vb.x; vv[dr][5] = vb.y;
    }

    float res[4];
    #pragma unroll
    for (int p = 0; p < 4; p++) {
        float den = 0.f, num = 0.f;
        #pragma unroll
        for (int dr = 0; dr < 3; dr++)
            #pragma unroll
            for (int dj = 0; dj < 3; dj++) {
                const float e = __expf(q[p] * (kk[dr][p + dj] + b9[dr * 3 + dj]));
                den += e;
                num = fmaf(e, vv[dr][p + dj], num);
            }
        res[p] = __fdividef(num, den);
    }

    *(float4*)(out + plane + h * WDIM + w0) = make_float4(res[0], res[1], res[2], res[3]);
}

// ---------------------------------------------------------------------------
extern "C" void kernel_launch(void* const* d_in, const int* in_sizes, int n_in,
                              void* d_out, int out_size)
{
    const float* x     = (const float*)d_in[0];
    const float* y     = (const float*)d_in[1];
    const float* wq    = (const float*)d_in[2];
    const float* wk    = (const float*)d_in[3];
    const float* wv    = (const float*)d_in[4];
    const float* rel_h = (const float*)d_in[5];
    const float* rel_w = (const float*)d_in[6];
    float* out = (float*)d_out;

    prep_w<<<dim3(64, 3), 256>>>(wq, wk, wv);

    dim3 ggrid(6, BATCH * HW / 128, 1);            // bx = z*2+m0, by = n0
    qkv_gemm_fp16<<<ggrid, 256>>>(x, y);

    dim3 agrid(HDIM / 16, COUT, BATCH);            // (4, 256, 8)
    attn_kernel2<<<agrid, 256>>>(rel_h, rel_w, out);
}

// round 16
// speedup vs baseline: 1.1295x; 1.0851x over previous
#include <cuda_runtime.h>
#include <cuda_fp16.h>
#include <cstdint>

#define CIN  256
#define COUT 256
#define HDIM 64
#define WDIM 64
#define HW   4096
#define BATCH 8

// Scratch — static device globals (alloc-free rule). q fp32; k,v fp16; W fp16.
__device__ __align__(128) float  g_q[(size_t)BATCH * COUT * HW];
__device__ __align__(128) __half g_kh[(size_t)BATCH * COUT * HW];
__device__ __align__(128) __half g_vh[(size_t)BATCH * COUT * HW];
__device__ __align__(128) __half g_wh[3 * 65536];

// ---------------------------------------------------------------------------
// helpers
// ---------------------------------------------------------------------------
__device__ __forceinline__ uint32_t f2h2(float a, float b) {
    uint32_t r;
    asm("cvt.rn.f16x2.f32 %0, %1, %2;" : "=r"(r) : "f"(b), "f"(a));
    return r;
}
__device__ __forceinline__ void h8_to_f8(uint4 u, float* f) {
    float2 p;
    p = __half22float2(*(__half2*)&u.x); f[0] = p.x; f[1] = p.y;
    p = __half22float2(*(__half2*)&u.y); f[2] = p.x; f[3] = p.y;
    p = __half22float2(*(__half2*)&u.z); f[4] = p.x; f[5] = p.y;
    p = __half22float2(*(__half2*)&u.w); f[6] = p.x; f[7] = p.y;
}

#define LDSM_X4(r0, r1, r2, r3, addr)                                           \
    asm volatile("ldmatrix.sync.aligned.m8n8.x4.shared.b16 {%0,%1,%2,%3}, [%4];"\
                 : "=r"(r0), "=r"(r1), "=r"(r2), "=r"(r3) : "r"(addr))

#define LDSM_X4_T(r0, r1, r2, r3, addr)                                         \
    asm volatile("ldmatrix.sync.aligned.m8n8.x4.trans.shared.b16 {%0,%1,%2,%3}, [%4];"\
                 : "=r"(r0), "=r"(r1), "=r"(r2), "=r"(r3) : "r"(addr))

#define MMAF16(d, a, b0, b1)                                                    \
    asm volatile("mma.sync.aligned.m16n8k16.row.col.f32.f16.f16.f32 "           \
        "{%0,%1,%2,%3}, {%4,%5,%6,%7}, {%8,%9}, {%0,%1,%2,%3};"                 \
        : "+f"((d)[0]), "+f"((d)[1]), "+f"((d)[2]), "+f"((d)[3])                \
        : "r"((a)[0]), "r"((a)[1]), "r"((a)[2]), "r"((a)[3]),                   \
          "r"(b0), "r"(b1))

#define CP16(dst, src)                                                          \
    asm volatile("cp.async.cg.shared.global [%0], [%1], 16;"                    \
                 :: "r"(dst), "l"(src) : "memory")
#define CP_COMMIT asm volatile("cp.async.commit_group;" ::: "memory")
#define CP_WAIT0  asm volatile("cp.async.wait_group 0;" ::: "memory")

// SMEM layout (bytes): A 128 rows x 264 halves (528 B/row) = 67584,
// then 2 B buffers of 32 x 136 halves (272 B/row) = 8704 each.
#define A_ROW_H   264
#define A_BYTES   (128 * 528)            // 67584
#define B_STRIDE  136
#define B_BYTES   (32 * 272)             // 8704
#define GEMM_SMEM (A_BYTES + 2 * B_BYTES)  // 84992

// ---------------------------------------------------------------------------
// Prep: convert W matrices to fp16. grid (64, 3), 256 threads.
// ---------------------------------------------------------------------------
__global__ __launch_bounds__(256)
void prep_w(const float* __restrict__ wq, const float* __restrict__ wk,
            const float* __restrict__ wv)
{
    const int z = blockIdx.y;
    const float* src = (z == 0) ? wq : (z == 1 ? wk : wv);
    const int i4 = blockIdx.x * 256 + threadIdx.x;
    const float4 a = *(const float4*)(src + i4 * 4);
    *(uint2*)(g_wh + z * 65536 + i4 * 4) =
        make_uint2(f2h2(a.x, a.y), f2h2(a.z, a.w));
}

// ---------------------------------------------------------------------------
// Persistent GEMM: 288 CTAs = 6 (z,m0) combos x 48 slots; each CTA loads its
// full-K fp16 A tile (128x256) into SMEM once, then loops over 5-6 n-tiles
// with a continuous B double-buffer pipeline (never drains across tiles).
// Slot t-assignment: slots 0-15 -> 6 tiles, slots 16-47 -> 5 (16*6+32*5=256).
// z=0: C=q fp32 (from y); z=1/2: C=k/v fp16 (from x).
// ---------------------------------------------------------------------------
__global__ __launch_bounds__(256, 2)
void qkv_gemm_persist(const float* __restrict__ x, const float* __restrict__ y)
{
    extern __shared__ __align__(16) char smem[];
    __half* Asm = (__half*)smem;
    char*   Bb  = smem + A_BYTES;

    const int zm   = blockIdx.x % 6;
    const int z    = zm >> 1;
    const int m0   = (zm & 1) * 128;
    const int slot = blockIdx.x / 6;
    const int tstart = (slot < 16) ? slot * 6 : 96 + (slot - 16) * 5;
    const int tcnt   = (slot < 16) ? 6 : 5;
    const int total  = tcnt * 8;            // k-block iterations

    const __half* Wh = g_wh + z * 65536;
    const float*  X  = (z == 0) ? y : x;

    const int tid  = threadIdx.x;
    const int lane = tid & 31;
    const int wid  = tid >> 5;
    const int wm   = (wid >> 1) * 32;
    const int wn   = (wid & 1) * 64;

    // B-load mapping: 4 float4/thread
    const int bcol = (tid & 31) * 4;
    const int brow = tid >> 5;

    // B source pointer for flattened k-block index bi
    auto bsrc_row = [&](int bi, int i) -> const float* {
        const int tile = bi >> 3;
        const int kb   = (bi & 7) * 32;
        const int n0   = (tstart + tile) * 128;
        const int b    = n0 >> 12;
        const int hw0  = n0 & 4095;
        return X + (size_t)b * CIN * HW + hw0 + (size_t)(kb + brow + i * 8) * HW + bcol;
    };

    float acc[2][8][4];
    #pragma unroll
    for (int i = 0; i < 2; i++)
        #pragma unroll
        for (int j = 0; j < 8; j++)
            #pragma unroll
            for (int q = 0; q < 4; q++)
                acc[i][j][q] = 0.0f;

    float4 rb[4];

    // ---- prologue ----
    // A: full 128x256 fp16 tile via 16 cp.async chunks/thread.
    {
        const uint32_t dA = (uint32_t)__cvta_generic_to_shared(Asm);
        #pragma unroll
        for (int i = 0; i < 16; i++) {
            const int cc  = tid + i * 256;     // chunk id, 32 chunks/row
            const int row = cc >> 5;
            const int sub = (cc & 31) * 8;     // halves
            CP16(dA + row * 528 + sub * 2, Wh + (m0 + row) * 256 + sub);
        }
        CP_COMMIT;
    }
    // B block 0 -> buf0 (regs, cvt, STS); B block 1 -> regs
    #pragma unroll
    for (int i = 0; i < 4; i++)
        rb[i] = *(const float4*)bsrc_row(0, i);
    #pragma unroll
    for (int i = 0; i < 4; i++)
        *(uint2*)(Bb + (brow + i * 8) * 272 + bcol * 2) =
            make_uint2(f2h2(rb[i].x, rb[i].y), f2h2(rb[i].z, rb[i].w));
    #pragma unroll
    for (int i = 0; i < 4; i++)
        rb[i] = *(const float4*)bsrc_row(1, i);
    CP_WAIT0;
    __syncthreads();

    for (int g = 0; g < total; g++) {
        const int it = g & 7;

        // STS: B block g+1 (in regs) -> buffer (g+1)&1.
        if (g + 1 < total) {
            char* dB = Bb + ((g + 1) & 1) * B_BYTES;
            #pragma unroll
            for (int i = 0; i < 4; i++)
                *(uint2*)(dB + (brow + i * 8) * 272 + bcol * 2) =
                    make_uint2(f2h2(rb[i].x, rb[i].y), f2h2(rb[i].z, rb[i].w));
        }
        // LDG: B block g+2 -> registers
        if (g + 2 < total) {
            #pragma unroll
            for (int i = 0; i < 4; i++)
                rb[i] = *(const float4*)bsrc_row(g + 2, i);
        }

        // ---- Compute: 2 ksteps of 16; A k-base = it*32 ----
        const uint32_t sA = (uint32_t)__cvta_generic_to_shared(Asm);
        const uint32_t sB = (uint32_t)__cvta_generic_to_shared(Bb + (g & 1) * B_BYTES);
        #pragma unroll
        for (int ks = 0; ks < 2; ks++) {
            const int kb = it * 32 + ks * 16;
            uint32_t af[2][4];
            #pragma unroll
            for (int mt = 0; mt < 2; mt++) {
                const uint32_t off =
                    (uint32_t)((wm + mt * 16 + (lane & 15)) * A_ROW_H + kb + (lane >> 4) * 8) * 2;
                LDSM_X4(af[mt][0], af[mt][1], af[mt][2], af[mt][3], sA + off);
            }
            #pragma unroll
            for (int ntp = 0; ntp < 4; ntp++) {
                const int nb = wn + ntp * 16;
                const uint32_t off =
                    (uint32_t)((ks * 16 + (lane & 15)) * B_STRIDE + nb + (lane >> 4) * 8) * 2;
                uint32_t bf[4];
                LDSM_X4_T(bf[0], bf[1], bf[2], bf[3], sB + off);
                #pragma unroll
                for (int mt = 0; mt < 2; mt++) {
                    #pragma unroll
                    for (int h2 = 0; h2 < 2; h2++)
                        MMAF16(acc[mt][ntp * 2 + h2], af[mt], bf[h2 * 2], bf[h2 * 2 + 1]);
                }
            }
        }

        // ---- Tile epilogue every 8 k-blocks ----
        if (it == 7) {
            const int tile = g >> 3;
            const int n0   = (tstart + tile) * 128;
            const int b    = n0 >> 12;
            const int hw0  = n0 & 4095;
            if (z == 0) {
                float* Cb = g_q + (size_t)b * COUT * HW + hw0;
                #pragma unroll
                for (int mt = 0; mt < 2; mt++) {
                    const int m = wm + mt * 16 + (lane >> 2);
                    #pragma unroll
                    for (int nt = 0; nt < 8; nt++) {
                        const int n = wn + nt * 8 + (lane & 3) * 2;
                        float* d = acc[mt][nt];
                        *(float2*)(Cb + (size_t)(m0 + m) * HW + n)     = make_float2(d[0], d[1]);
                        *(float2*)(Cb + (size_t)(m0 + m + 8) * HW + n) = make_float2(d[2], d[3]);
                        d[0] = d[1] = d[2] = d[3] = 0.0f;
                    }
                }
            } else {
                __half* Hb = ((z == 1) ? g_kh : g_vh) + (size_t)b * COUT * HW + hw0;
                #pragma unroll
                for (int mt = 0; mt < 2; mt++) {
                    const int m = wm + mt * 16 + (lane >> 2);
                    #pragma unroll
                    for (int nt = 0; nt < 8; nt++) {
                        const int n = wn + nt * 8 + (lane & 3) * 2;
                        float* d = acc[mt][nt];
                        *(uint32_t*)(Hb + (size_t)(m0 + m) * HW + n)     = f2h2(d[0], d[1]);
                        *(uint32_t*)(Hb + (size_t)(m0 + m + 8) * HW + n) = f2h2(d[2], d[3]);
                        d[0] = d[1] = d[2] = d[3] = 0.0f;
                    }
                }
            }
        }
        __syncthreads();
    }
}

// ---------------------------------------------------------------------------
// Window attention: SMEM-tiled, 4 px/thread, zero halo, no max-subtraction.
// q fp32; k,v fp16 (converted to fp32 during the single-pass SMEM fill).
// ---------------------------------------------------------------------------
__global__ __launch_bounds__(256)
void attn_kernel2(const float* __restrict__ rel_h, const float* __restrict__ rel_w,
                  float* __restrict__ out)
{
    __shared__ float Ks[18][68];
    __shared__ float Vs[18][68];

    const int tid = threadIdx.x;
    const int h0  = blockIdx.x * 16;
    const int c   = blockIdx.y;
    const int b   = blockIdx.z;
    const size_t plane = ((size_t)b * COUT + c) * HW;
    const __half* kp = g_kh + plane;
    const __half* vp = g_vh + plane;

    if (tid < 144) {
        const int r   = tid >> 3;
        const int seg = (tid & 7) * 8;
        const int gh  = h0 - 1 + r;
        float kf[8] = {0, 0, 0, 0, 0, 0, 0, 0};
        float vf[8] = {0, 0, 0, 0, 0, 0, 0, 0};
        if ((unsigned)gh < (unsigned)HDIM) {
            h8_to_f8(*(const uint4*)(kp + gh * WDIM + seg), kf);
            h8_to_f8(*(const uint4*)(vp + gh * WDIM + seg), vf);
        }
        #pragma unroll
        for (int j = 0; j < 8; j++) {
            Ks[r][seg + 1 + j] = kf[j];
            Vs[r][seg + 1 + j] = vf[j];
        }
    }
    if (tid < 18) {
        Ks[tid][0] = 0.f; Ks[tid][65] = 0.f;
        Vs[tid][0] = 0.f; Vs[tid][65] = 0.f;
    }

    float b9[9];
    {
        const bool use_h = (c < 128);
        float bias[3];
        if (use_h) {
            bias[0] = rel_h[c * 3 + 0]; bias[1] = rel_h[c * 3 + 1]; bias[2] = rel_h[c * 3 + 2];
        } else {
            bias[0] = rel_w[(c - 128) * 3 + 0]; bias[1] = rel_w[(c - 128) * 3 + 1];
            bias[2] = rel_w[(c - 128) * 3 + 2];
        }
        #pragma unroll
        for (int dr = 0; dr < 3; dr++)
            #pragma unroll
            for (int dj = 0; dj < 3; dj++)
                b9[dr * 3 + dj] = use_h ? bias[dr] : bias[dj];
    }
    __syncthreads();

    const int lr = tid >> 4;
    const int w0 = (tid & 15) * 4;
    const int h  = h0 + lr;

    const float4 q4 = *(const float4*)(g_q + plane + h * WDIM + w0);
    const float q[4] = {q4.x, q4.y, q4.z, q4.w};

    float kk[3][6], vv[3][6];
    #pragma unroll
    for (int dr = 0; dr < 3; dr++) {
        const float* krow = &Ks[lr + dr][w0];
        const float* vrow = &Vs[lr + dr][w0];
        const float4 ka = *(const float4*)krow;
        const float2 kb = *(const float2*)(krow + 4);
        const float4 va = *(const float4*)vrow;
        const float2 vb = *(const float2*)(vrow + 4);
        kk[dr][0] = ka.x; kk[dr][1] = ka.y; kk[dr][2] = ka.z;
        kk[dr][3] = ka.w; kk[dr][4] = kb.x; kk[dr][5] = kb.y;
        vv[dr][0] = va.x; vv[dr][1] = va.y; vv[dr][2] = va.z;
        vv[dr][3] = va.w; vv[dr][4] = vb.x; vv[dr][5] = vb.y;
    }

    float res[4];
    #pragma unroll
    for (int p = 0; p < 4; p++) {
        float den = 0.f, num = 0.f;
        #pragma unroll
        for (int dr = 0; dr < 3; dr++)
            #pragma unroll
            for (int dj = 0; dj < 3; dj++) {
                const float e = __expf(q[p] * (kk[dr][p + dj] + b9[dr * 3 + dj]));
                den += e;
                num = fmaf(e, vv[dr][p + dj], num);
            }
        res[p] = __fdividef(num, den);
    }

    *(float4*)(out + plane + h * WDIM + w0) = make_float4(res[0], res[1], res[2], res[3]);
}

// ---------------------------------------------------------------------------
extern "C" void kernel_launch(void* const* d_in, const int* in_sizes, int n_in,
                              void* d_out, int out_size)
{
    const float* x     = (const float*)d_in[0];
    const float* y     = (const float*)d_in[1];
    const float* wq    = (const float*)d_in[2];
    const float* wk    = (const float*)d_in[3];
    const float* wv    = (const float*)d_in[4];
    const float* rel_h = (const float*)d_in[5];
    const float* rel_w = (const float*)d_in[6];
    float* out = (float*)d_out;

    cudaFuncSetAttribute(qkv_gemm_persist,
                         cudaFuncAttributeMaxDynamicSharedMemorySize, GEMM_SMEM);

    prep_w<<<dim3(64, 3), 256>>>(wq, wk, wv);

    qkv_gemm_persist<<<288, 256, GEMM_SMEM>>>(x, y);

    dim3 agrid(HDIM / 16, COUT, BATCH);            // (4, 256, 8)
    attn_kernel2<<<agrid, 256>>>(rel_h, rel_w, out);
}